// round 4
// baseline (speedup 1.0000x reference)
#include <cuda_runtime.h>

// ---------------------------------------------------------------------------
// Problem constants
//   x: (4, 5280, 1024) fp32.  M = 21120 token rows, C = 1024, H=16, D=64.
//   Spatial attention: 96 seqs of len 220.  Temporal: 880 seqs of len 24.
// ---------------------------------------------------------------------------
#define K_DIM 1024
#define BM 128
#define BN 128
#define BKK 16

// Scratch (static __device__ arrays — no allocation allowed)
__device__ float g_bufA[64880640ull];  // 21120 * 3072  (qkv)
__device__ float g_bufB[21626880ull];  // 21120 * 1024
__device__ float g_bufC[21626880ull];  // 21120 * 1024

// ---------------------------------------------------------------------------
// Packed fp32x2 helpers (Blackwell FFMA2 path — 2x fp32 FMA throughput)
// ---------------------------------------------------------------------------
__device__ __forceinline__ unsigned long long pk2(float v) {
    unsigned long long r;
    asm("mov.b64 %0, {%1, %1};" : "=l"(r) : "f"(v));
    return r;
}
__device__ __forceinline__ float2 upk(unsigned long long v) {
    float lo, hi;
    asm("mov.b64 {%0, %1}, %2;" : "=f"(lo), "=f"(hi) : "l"(v));
    return make_float2(lo, hi);
}
__device__ __forceinline__ void ffma2(unsigned long long& d, unsigned long long a,
                                      unsigned long long b) {
    asm("fma.rn.f32x2 %0, %1, %2, %0;" : "+l"(d) : "l"(a), "l"(b));
}

// ---------------------------------------------------------------------------
// SGEMM:  C[M,N] = A[M,K] * W[N,K]^T  (+ optional bias[N])
// 128x128x16 tiles, 256 threads, 8x8 per thread (split 4+4 rows/cols),
// double-buffered shared memory, f32x2 packed accumulation.
// M is given by gridDim.y*128 (always 21120 here), K = 1024.
// ---------------------------------------------------------------------------
__global__ __launch_bounds__(256, 2)
void sgemm_nt(const float* __restrict__ A, const float* __restrict__ W,
              float* __restrict__ C, const float* __restrict__ bias, int N)
{
    __shared__ float As[2][BKK][132];   // [k][m], padded to 132 (bank + f4 align)
    __shared__ float Bs[2][BKK][132];   // [k][n]

    const int tid = threadIdx.x;
    const int m0 = blockIdx.y * BM;
    const int n0 = blockIdx.x * BN;

    // tile loaders: each thread loads 2 float4 from A and 2 from W per k-tile
    const int lrow = tid >> 2;          // 0..63
    const int lcol = (tid & 3) << 2;    // 0,4,8,12

    const float* pa0 = A + (size_t)(m0 + lrow) * K_DIM + lcol;
    const float* pa1 = pa0 + (size_t)64 * K_DIM;
    const float* pb0 = W + (size_t)(n0 + lrow) * K_DIM + lcol;
    const float* pb1 = pb0 + (size_t)64 * K_DIM;

    { // prologue: tile 0 -> buffer 0 (transposed store)
        float4 a0 = *(const float4*)pa0;
        float4 a1 = *(const float4*)pa1;
        float4 w0 = *(const float4*)pb0;
        float4 w1 = *(const float4*)pb1;
        pa0 += BKK; pa1 += BKK; pb0 += BKK; pb1 += BKK;
#pragma unroll
        for (int i = 0; i < 4; i++) {
            As[0][lcol + i][lrow]      = ((const float*)&a0)[i];
            As[0][lcol + i][lrow + 64] = ((const float*)&a1)[i];
            Bs[0][lcol + i][lrow]      = ((const float*)&w0)[i];
            Bs[0][lcol + i][lrow + 64] = ((const float*)&w1)[i];
        }
    }
    __syncthreads();

    const int ty = tid >> 4;            // 0..15
    const int tx = tid & 15;            // 0..15
    const int rbase = ty * 4;           // rows rbase..+3 and rbase+64..+67
    const int cbase = tx * 4;           // cols cbase..+3 and cbase+64..+67

    unsigned long long acc[8][4];
#pragma unroll
    for (int i = 0; i < 8; i++)
#pragma unroll
        for (int j = 0; j < 4; j++) acc[i][j] = 0ull;

    const int nk = K_DIM / BKK;         // 64
    int buf = 0;
    for (int t = 0; t < nk; ++t) {
        float4 a0, a1, w0, w1;
        const bool pre = (t + 1 < nk);
        if (pre) {
            a0 = *(const float4*)pa0;
            a1 = *(const float4*)pa1;
            w0 = *(const float4*)pb0;
            w1 = *(const float4*)pb1;
            pa0 += BKK; pa1 += BKK; pb0 += BKK; pb1 += BKK;
        }
#pragma unroll
        for (int kk = 0; kk < BKK; ++kk) {
            const float* ar = &As[buf][kk][0];
            const float* br = &Bs[buf][kk][0];
            float4 aLo = *(const float4*)(ar + rbase);
            float4 aHi = *(const float4*)(ar + rbase + 64);
            unsigned long long b0 = *(const unsigned long long*)(br + cbase);
            unsigned long long b1 = *(const unsigned long long*)(br + cbase + 2);
            unsigned long long b2 = *(const unsigned long long*)(br + cbase + 64);
            unsigned long long b3 = *(const unsigned long long*)(br + cbase + 66);
#pragma unroll
            for (int i = 0; i < 8; i++) {
                float av = (i < 4) ? ((const float*)&aLo)[i] : ((const float*)&aHi)[i - 4];
                unsigned long long a2 = pk2(av);
                ffma2(acc[i][0], a2, b0);
                ffma2(acc[i][1], a2, b1);
                ffma2(acc[i][2], a2, b2);
                ffma2(acc[i][3], a2, b3);
            }
        }
        if (pre) {
            const int nb = buf ^ 1;
#pragma unroll
            for (int i = 0; i < 4; i++) {
                As[nb][lcol + i][lrow]      = ((const float*)&a0)[i];
                As[nb][lcol + i][lrow + 64] = ((const float*)&a1)[i];
                Bs[nb][lcol + i][lrow]      = ((const float*)&w0)[i];
                Bs[nb][lcol + i][lrow + 64] = ((const float*)&w1)[i];
            }
        }
        __syncthreads();
        buf ^= 1;
    }

    // epilogue (+ bias)
    float2 bv0 = make_float2(0.f, 0.f), bv1 = bv0, bv2 = bv0, bv3 = bv0;
    if (bias) {
        bv0 = *(const float2*)(bias + n0 + cbase);
        bv1 = *(const float2*)(bias + n0 + cbase + 2);
        bv2 = *(const float2*)(bias + n0 + cbase + 64);
        bv3 = *(const float2*)(bias + n0 + cbase + 66);
    }
#pragma unroll
    for (int i = 0; i < 8; i++) {
        const int mrow = m0 + rbase + (i & 3) + ((i & 4) ? 64 : 0);
        float* cp = C + (size_t)mrow * N + n0;
        float2 v0 = upk(acc[i][0]);
        float2 v1 = upk(acc[i][1]);
        float2 v2 = upk(acc[i][2]);
        float2 v3 = upk(acc[i][3]);
        v0.x += bv0.x; v0.y += bv0.y;
        v1.x += bv1.x; v1.y += bv1.y;
        v2.x += bv2.x; v2.y += bv2.y;
        v3.x += bv3.x; v3.y += bv3.y;
        *(float4*)(cp + cbase)      = make_float4(v0.x, v0.y, v1.x, v1.y);
        *(float4*)(cp + cbase + 64) = make_float4(v2.x, v2.y, v3.x, v3.y);
    }
}

// ---------------------------------------------------------------------------
// Fused RMSNorm + RoPE, in place on q and k components of qkv (M x 3072).
// One warp per (row, component, head). 64-wide head handled as float2/lane.
// pos = row % seqlen (valid for both spatial and temporal row layouts).
// ---------------------------------------------------------------------------
__global__ void norm_rope(float* __restrict__ qkv, const float* __restrict__ qg,
                          const float* __restrict__ kg, int seqlen)
{
    const int warp = (blockIdx.x << 3) + (threadIdx.x >> 5);
    const int lane = threadIdx.x & 31;
    const int row  = warp >> 5;
    const int rem  = warp & 31;
    const int comp = rem >> 4;   // 0 = q, 1 = k
    const int head = rem & 15;

    float* p = qkv + (size_t)row * 3072 + comp * 1024 + head * 64 + 2 * lane;
    float2 v = *(float2*)p;
    float ss = v.x * v.x + v.y * v.y;
#pragma unroll
    for (int o = 16; o > 0; o >>= 1) ss += __shfl_xor_sync(0xffffffffu, ss, o);
    const float inv = rsqrtf(ss * (1.0f / 64.0f) + 1e-6f);

    const float* g = comp ? kg : qg;
    const float x0 = v.x * inv * g[2 * lane];
    const float x1 = v.y * inv * g[2 * lane + 1];

    const int pos = row % seqlen;
    // theta_j = 10000^(-2j/64) = 2^(-j * log2(1e4)/32),  j = lane
    const float theta = exp2f((float)lane * (-13.287712379549449f / 32.0f));
    float s, c;
    sincosf((float)pos * theta, &s, &c);
    *(float2*)p = make_float2(x0 * c - x1 * s, x1 * c + x0 * s);
}

// ---------------------------------------------------------------------------
// Attention: one CTA per (head, sequence).  K,V staged in padded smem
// (stride 65 -> conflict-free lane-s access).  One warp per q row:
// lane-parallel scores over s, warp softmax, then lane-parallel over d.
// out layout: (M, 1024) with out[(n*S+s)*1024 + h*64 + d].
// ---------------------------------------------------------------------------
__global__ void attn_kernel(const float* __restrict__ qkv, float* __restrict__ out, int S)
{
    extern __shared__ float sm[];
    const int h = blockIdx.x;
    const int n = blockIdx.y;
    const int tid = threadIdx.x;
    const int w = tid >> 5;
    const int lane = tid & 31;

    float* sK = sm;                 // S * 65
    float* sV = sK + S * 65;        // S * 65
    float* sP = sV + S * 65;        // 8 * S  (per-warp prob rows)
    float* sQ = sP + 8 * S;         // 8 * 64 (per-warp q rows)

    const float* base = qkv + (size_t)n * S * 3072 + h * 64;
    for (int idx = tid; idx < S * 64; idx += 256) {
        const int s = idx >> 6, d = idx & 63;
        sK[s * 65 + d] = base[(size_t)s * 3072 + 1024 + d];
        sV[s * 65 + d] = base[(size_t)s * 3072 + 2048 + d];
    }
    __syncthreads();

    for (int r = w; r < S; r += 8) {
        {
            float2 q2 = *(const float2*)(base + (size_t)r * 3072 + 2 * lane);
            sQ[w * 64 + 2 * lane]     = q2.x;
            sQ[w * 64 + 2 * lane + 1] = q2.y;
        }
        __syncwarp();

        float sc[7];                 // ceil(220/32) = 7 max
        float mx = -1e30f;
        int cnt = 0;
        for (int s = lane; s < S; s += 32) {
            float dot = 0.f;
            const float* kr = sK + s * 65;
            const float* qr = sQ + w * 64;
#pragma unroll
            for (int d = 0; d < 64; d++) dot = fmaf(qr[d], kr[d], dot);
            dot *= 0.125f;           // 1/sqrt(64)
            sc[cnt++] = dot;
            mx = fmaxf(mx, dot);
        }
#pragma unroll
        for (int o = 16; o > 0; o >>= 1) mx = fmaxf(mx, __shfl_xor_sync(0xffffffffu, mx, o));
        float sum = 0.f;
#pragma unroll
        for (int i = 0; i < 7; i++)
            if (i < cnt) { sc[i] = __expf(sc[i] - mx); sum += sc[i]; }
#pragma unroll
        for (int o = 16; o > 0; o >>= 1) sum += __shfl_xor_sync(0xffffffffu, sum, o);
        const float isum = 1.0f / sum;
        {
            int i = 0;
            for (int s = lane; s < S; s += 32) sP[w * S + s] = sc[i++] * isum;
        }
        __syncwarp();

        float a0 = 0.f, a1 = 0.f;
        const float* pw = sP + w * S;
        for (int s = 0; s < S; s++) {
            const float pp = pw[s];
            a0 = fmaf(pp, sV[s * 65 + lane], a0);
            a1 = fmaf(pp, sV[s * 65 + lane + 32], a1);
        }
        float* op = out + ((size_t)n * S + r) * 1024 + h * 64;
        op[lane]      = a0;
        op[lane + 32] = a1;
        __syncwarp();
    }
}

// ---------------------------------------------------------------------------
// Row permutes between spatial layout  rs = (b*24+f)*220+p
// and temporal layout                  rt = (b*220+p)*24+f.
// Rows are contiguous 1024 floats -> fully coalesced both sides.
// ---------------------------------------------------------------------------
__global__ void s2t_kernel(const float* __restrict__ src, float* __restrict__ dst)
{
    const int rt = blockIdx.x;
    const int f = rt % 24;
    const int bp = rt / 24;
    const int p = bp % 220;
    const int b = bp / 220;
    const int rs = (b * 24 + f) * 220 + p;
    const float4* s = (const float4*)(src + (size_t)rs * 1024);
    float4* d = (float4*)(dst + (size_t)rt * 1024);
    d[threadIdx.x] = s[threadIdx.x];
}
__global__ void t2s_kernel(const float* __restrict__ src, float* __restrict__ dst)
{
    const int rs = blockIdx.x;
    const int p = rs % 220;
    const int bf = rs / 220;
    const int f = bf % 24;
    const int b = bf / 24;
    const int rt = (b * 220 + p) * 24 + f;
    const float4* s = (const float4*)(src + (size_t)rt * 1024);
    float4* d = (float4*)(dst + (size_t)rs * 1024);
    d[threadIdx.x] = s[threadIdx.x];
}

// ---------------------------------------------------------------------------
// Orchestration (graph-capturable: kernel launches only)
// ---------------------------------------------------------------------------
extern "C" void kernel_launch(void* const* d_in, const int* in_sizes, int n_in,
                              void* d_out, int out_size)
{
    (void)in_sizes; (void)n_in; (void)out_size;
    const float* x       = (const float*)d_in[0];
    const float* w_sqkv  = (const float*)d_in[1];
    const float* w_sproj = (const float*)d_in[2];
    const float* b_sproj = (const float*)d_in[3];
    const float* w_tqkv  = (const float*)d_in[4];
    const float* w_tproj = (const float*)d_in[5];
    const float* b_tproj = (const float*)d_in[6];
    const float* sqg     = (const float*)d_in[7];
    const float* skg     = (const float*)d_in[8];
    const float* tqg     = (const float*)d_in[9];
    const float* tkg     = (const float*)d_in[10];
    float* out = (float*)d_out;

    float *bufA = nullptr, *bufB = nullptr, *bufC = nullptr;
    cudaGetSymbolAddress((void**)&bufA, g_bufA);
    cudaGetSymbolAddress((void**)&bufB, g_bufB);
    cudaGetSymbolAddress((void**)&bufC, g_bufC);

    const int M = 21120;
    const size_t smemS = (size_t)(2 * 220 * 65 + 8 * 220 + 512) * sizeof(float); // ~120.6 KB
    const size_t smemT = (size_t)(2 * 24 * 65 + 8 * 24 + 512) * sizeof(float);
    cudaFuncSetAttribute((const void*)attn_kernel,
                         cudaFuncAttributeMaxDynamicSharedMemorySize, (int)smemS);

    dim3 blk(256);

    // ---- spatial block (spatial row layout == input layout) ----
    sgemm_nt<<<dim3(24, M / 128), blk>>>(x, w_sqkv, bufA, nullptr, 3072);
    norm_rope<<<M * 4, blk>>>(bufA, sqg, skg, 220);
    attn_kernel<<<dim3(16, 96), blk, smemS>>>(bufA, bufB, 220);
    sgemm_nt<<<dim3(8, M / 128), blk>>>(bufB, w_sproj, bufC, b_sproj, 1024);

    // ---- spatial -> temporal layout ----
    s2t_kernel<<<M, blk>>>(bufC, bufB);

    // ---- temporal block ----
    sgemm_nt<<<dim3(24, M / 128), blk>>>(bufB, w_tqkv, bufA, nullptr, 3072);
    norm_rope<<<M * 4, blk>>>(bufA, tqg, tkg, 24);
    attn_kernel<<<dim3(16, 880), blk, smemT>>>(bufA, bufB, 24);
    sgemm_nt<<<dim3(8, M / 128), blk>>>(bufB, w_tproj, bufC, b_tproj, 1024);

    // ---- temporal -> output (spatial) layout ----
    t2s_kernel<<<M, blk>>>(bufC, out);
}

// round 5
// speedup vs baseline: 1.6044x; 1.6044x over previous
#include <cuda_runtime.h>

// ---------------------------------------------------------------------------
// Problem constants
//   x: (4, 5280, 1024) fp32.  M = 21120 token rows, C = 1024, H=16, D=64.
//   Spatial attention: 96 seqs of len 220.  Temporal: 880 seqs of len 24.
// ---------------------------------------------------------------------------
#define K_DIM 1024
#define BM 128
#define BN 128
#define BKK 16

// Scratch (static __device__ arrays — no allocation allowed)
__device__ float g_bufA[64880640ull];  // 21120 * 3072  (qkv)
__device__ float g_bufB[21626880ull];  // 21120 * 1024
__device__ float g_bufC[21626880ull];  // 21120 * 1024

// ---------------------------------------------------------------------------
// Packed fp32x2 helpers (Blackwell FFMA2 path — 2x fp32 FMA throughput)
// ---------------------------------------------------------------------------
__device__ __forceinline__ unsigned long long pk2(float v) {
    unsigned long long r;
    asm("mov.b64 %0, {%1, %1};" : "=l"(r) : "f"(v));
    return r;
}
__device__ __forceinline__ float2 upk(unsigned long long v) {
    float lo, hi;
    asm("mov.b64 {%0, %1}, %2;" : "=f"(lo), "=f"(hi) : "l"(v));
    return make_float2(lo, hi);
}
__device__ __forceinline__ void ffma2(unsigned long long& d, unsigned long long a,
                                      unsigned long long b) {
    asm("fma.rn.f32x2 %0, %1, %2, %0;" : "+l"(d) : "l"(a), "l"(b));
}

// ---------------------------------------------------------------------------
// SGEMM:  C[M,N] = A[M,K] * W[N,K]^T  (+ optional bias[N])
// 128x128x16 tiles, 256 threads, 8x8 per thread (split 4+4 rows/cols),
// double-buffered shared memory, f32x2 packed accumulation.
// M is given by gridDim.y*128 (always 21120 here), K = 1024.
// ---------------------------------------------------------------------------
__global__ __launch_bounds__(256, 2)
void sgemm_nt(const float* __restrict__ A, const float* __restrict__ W,
              float* __restrict__ C, const float* __restrict__ bias, int N)
{
    __shared__ float As[2][BKK][132];   // [k][m], padded to 132 (bank + f4 align)
    __shared__ float Bs[2][BKK][132];   // [k][n]

    const int tid = threadIdx.x;
    const int m0 = blockIdx.y * BM;
    const int n0 = blockIdx.x * BN;

    // tile loaders: each thread loads 2 float4 from A and 2 from W per k-tile
    const int lrow = tid >> 2;          // 0..63
    const int lcol = (tid & 3) << 2;    // 0,4,8,12

    const float* pa0 = A + (size_t)(m0 + lrow) * K_DIM + lcol;
    const float* pa1 = pa0 + (size_t)64 * K_DIM;
    const float* pb0 = W + (size_t)(n0 + lrow) * K_DIM + lcol;
    const float* pb1 = pb0 + (size_t)64 * K_DIM;

    { // prologue: tile 0 -> buffer 0 (transposed store)
        float4 a0 = *(const float4*)pa0;
        float4 a1 = *(const float4*)pa1;
        float4 w0 = *(const float4*)pb0;
        float4 w1 = *(const float4*)pb1;
        pa0 += BKK; pa1 += BKK; pb0 += BKK; pb1 += BKK;
#pragma unroll
        for (int i = 0; i < 4; i++) {
            As[0][lcol + i][lrow]      = ((const float*)&a0)[i];
            As[0][lcol + i][lrow + 64] = ((const float*)&a1)[i];
            Bs[0][lcol + i][lrow]      = ((const float*)&w0)[i];
            Bs[0][lcol + i][lrow + 64] = ((const float*)&w1)[i];
        }
    }
    __syncthreads();

    const int ty = tid >> 4;            // 0..15
    const int tx = tid & 15;            // 0..15
    const int rbase = ty * 4;           // rows rbase..+3 and rbase+64..+67
    const int cbase = tx * 4;           // cols cbase..+3 and cbase+64..+67

    unsigned long long acc[8][4];
#pragma unroll
    for (int i = 0; i < 8; i++)
#pragma unroll
        for (int j = 0; j < 4; j++) acc[i][j] = 0ull;

    const int nk = K_DIM / BKK;         // 64
    int buf = 0;
    for (int t = 0; t < nk; ++t) {
        float4 a0, a1, w0, w1;
        const bool pre = (t + 1 < nk);
        if (pre) {
            a0 = *(const float4*)pa0;
            a1 = *(const float4*)pa1;
            w0 = *(const float4*)pb0;
            w1 = *(const float4*)pb1;
            pa0 += BKK; pa1 += BKK; pb0 += BKK; pb1 += BKK;
        }
#pragma unroll
        for (int kk = 0; kk < BKK; ++kk) {
            const float* ar = &As[buf][kk][0];
            const float* br = &Bs[buf][kk][0];
            float4 aLo = *(const float4*)(ar + rbase);
            float4 aHi = *(const float4*)(ar + rbase + 64);
            unsigned long long b0 = *(const unsigned long long*)(br + cbase);
            unsigned long long b1 = *(const unsigned long long*)(br + cbase + 2);
            unsigned long long b2 = *(const unsigned long long*)(br + cbase + 64);
            unsigned long long b3 = *(const unsigned long long*)(br + cbase + 66);
#pragma unroll
            for (int i = 0; i < 8; i++) {
                float av = (i < 4) ? ((const float*)&aLo)[i] : ((const float*)&aHi)[i - 4];
                unsigned long long a2 = pk2(av);
                ffma2(acc[i][0], a2, b0);
                ffma2(acc[i][1], a2, b1);
                ffma2(acc[i][2], a2, b2);
                ffma2(acc[i][3], a2, b3);
            }
        }
        if (pre) {
            const int nb = buf ^ 1;
#pragma unroll
            for (int i = 0; i < 4; i++) {
                As[nb][lcol + i][lrow]      = ((const float*)&a0)[i];
                As[nb][lcol + i][lrow + 64] = ((const float*)&a1)[i];
                Bs[nb][lcol + i][lrow]      = ((const float*)&w0)[i];
                Bs[nb][lcol + i][lrow + 64] = ((const float*)&w1)[i];
            }
        }
        __syncthreads();
        buf ^= 1;
    }

    // epilogue (+ bias)
    float2 bv0 = make_float2(0.f, 0.f), bv1 = bv0, bv2 = bv0, bv3 = bv0;
    if (bias) {
        bv0 = *(const float2*)(bias + n0 + cbase);
        bv1 = *(const float2*)(bias + n0 + cbase + 2);
        bv2 = *(const float2*)(bias + n0 + cbase + 64);
        bv3 = *(const float2*)(bias + n0 + cbase + 66);
    }
#pragma unroll
    for (int i = 0; i < 8; i++) {
        const int mrow = m0 + rbase + (i & 3) + ((i & 4) ? 64 : 0);
        float* cp = C + (size_t)mrow * N + n0;
        float2 v0 = upk(acc[i][0]);
        float2 v1 = upk(acc[i][1]);
        float2 v2 = upk(acc[i][2]);
        float2 v3 = upk(acc[i][3]);
        v0.x += bv0.x; v0.y += bv0.y;
        v1.x += bv1.x; v1.y += bv1.y;
        v2.x += bv2.x; v2.y += bv2.y;
        v3.x += bv3.x; v3.y += bv3.y;
        *(float4*)(cp + cbase)      = make_float4(v0.x, v0.y, v1.x, v1.y);
        *(float4*)(cp + cbase + 64) = make_float4(v2.x, v2.y, v3.x, v3.y);
    }
}

// ---------------------------------------------------------------------------
// Fused RMSNorm + RoPE, in place on q and k components of qkv (M x 3072).
// One warp per (row, component, head). 64-wide head handled as float2/lane.
// pos = row % seqlen (valid for both spatial and temporal row layouts).
// ---------------------------------------------------------------------------
__global__ void norm_rope(float* __restrict__ qkv, const float* __restrict__ qg,
                          const float* __restrict__ kg, int seqlen)
{
    const int warp = (blockIdx.x << 3) + (threadIdx.x >> 5);
    const int lane = threadIdx.x & 31;
    const int row  = warp >> 5;
    const int rem  = warp & 31;
    const int comp = rem >> 4;   // 0 = q, 1 = k
    const int head = rem & 15;

    float* p = qkv + (size_t)row * 3072 + comp * 1024 + head * 64 + 2 * lane;
    float2 v = *(float2*)p;
    float ss = v.x * v.x + v.y * v.y;
#pragma unroll
    for (int o = 16; o > 0; o >>= 1) ss += __shfl_xor_sync(0xffffffffu, ss, o);
    const float inv = rsqrtf(ss * (1.0f / 64.0f) + 1e-6f);

    const float* g = comp ? kg : qg;
    const float x0 = v.x * inv * g[2 * lane];
    const float x1 = v.y * inv * g[2 * lane + 1];

    const int pos = row % seqlen;
    // theta_j = 10000^(-2j/64) = 2^(-j * log2(1e4)/32),  j = lane
    const float theta = exp2f((float)lane * (-13.287712379549449f / 32.0f));
    float s, c;
    sincosf((float)pos * theta, &s, &c);
    *(float2*)p = make_float2(x0 * c - x1 * s, x1 * c + x0 * s);
}

// ---------------------------------------------------------------------------
// Attention: one CTA per (head, sequence).  K,V staged in padded smem
// (stride 65 -> conflict-free lane-s access).  One warp per q row:
// lane-parallel scores over s, warp softmax, then lane-parallel over d.
// out layout: (M, 1024) with out[(n*S+s)*1024 + h*64 + d].
// ---------------------------------------------------------------------------
__global__ void attn_kernel(const float* __restrict__ qkv, float* __restrict__ out, int S)
{
    extern __shared__ float sm[];
    const int h = blockIdx.x;
    const int n = blockIdx.y;
    const int tid = threadIdx.x;
    const int w = tid >> 5;
    const int lane = tid & 31;

    float* sK = sm;                 // S * 65
    float* sV = sK + S * 65;        // S * 65
    float* sP = sV + S * 65;        // 8 * S  (per-warp prob rows)
    float* sQ = sP + 8 * S;         // 8 * 64 (per-warp q rows)

    const float* base = qkv + (size_t)n * S * 3072 + h * 64;
    for (int idx = tid; idx < S * 64; idx += 256) {
        const int s = idx >> 6, d = idx & 63;
        sK[s * 65 + d] = base[(size_t)s * 3072 + 1024 + d];
        sV[s * 65 + d] = base[(size_t)s * 3072 + 2048 + d];
    }
    __syncthreads();

    for (int r = w; r < S; r += 8) {
        {
            float2 q2 = *(const float2*)(base + (size_t)r * 3072 + 2 * lane);
            sQ[w * 64 + 2 * lane]     = q2.x;
            sQ[w * 64 + 2 * lane + 1] = q2.y;
        }
        __syncwarp();

        float sc[7];                 // ceil(220/32) = 7 max
        float mx = -1e30f;
        int cnt = 0;
        for (int s = lane; s < S; s += 32) {
            float dot = 0.f;
            const float* kr = sK + s * 65;
            const float* qr = sQ + w * 64;
#pragma unroll
            for (int d = 0; d < 64; d++) dot = fmaf(qr[d], kr[d], dot);
            dot *= 0.125f;           // 1/sqrt(64)
            sc[cnt++] = dot;
            mx = fmaxf(mx, dot);
        }
#pragma unroll
        for (int o = 16; o > 0; o >>= 1) mx = fmaxf(mx, __shfl_xor_sync(0xffffffffu, mx, o));
        float sum = 0.f;
#pragma unroll
        for (int i = 0; i < 7; i++)
            if (i < cnt) { sc[i] = __expf(sc[i] - mx); sum += sc[i]; }
#pragma unroll
        for (int o = 16; o > 0; o >>= 1) sum += __shfl_xor_sync(0xffffffffu, sum, o);
        const float isum = 1.0f / sum;
        {
            int i = 0;
            for (int s = lane; s < S; s += 32) sP[w * S + s] = sc[i++] * isum;
        }
        __syncwarp();

        float a0 = 0.f, a1 = 0.f;
        const float* pw = sP + w * S;
        for (int s = 0; s < S; s++) {
            const float pp = pw[s];
            a0 = fmaf(pp, sV[s * 65 + lane], a0);
            a1 = fmaf(pp, sV[s * 65 + lane + 32], a1);
        }
        float* op = out + ((size_t)n * S + r) * 1024 + h * 64;
        op[lane]      = a0;
        op[lane + 32] = a1;
        __syncwarp();
    }
}

// ---------------------------------------------------------------------------
// Row permutes between spatial layout  rs = (b*24+f)*220+p
// and temporal layout                  rt = (b*220+p)*24+f.
// Rows are contiguous 1024 floats -> fully coalesced both sides.
// ---------------------------------------------------------------------------
__global__ void s2t_kernel(const float* __restrict__ src, float* __restrict__ dst)
{
    const int rt = blockIdx.x;
    const int f = rt % 24;
    const int bp = rt / 24;
    const int p = bp % 220;
    const int b = bp / 220;
    const int rs = (b * 24 + f) * 220 + p;
    const float4* s = (const float4*)(src + (size_t)rs * 1024);
    float4* d = (float4*)(dst + (size_t)rt * 1024);
    d[threadIdx.x] = s[threadIdx.x];
}
__global__ void t2s_kernel(const float* __restrict__ src, float* __restrict__ dst)
{
    const int rs = blockIdx.x;
    const int p = rs % 220;
    const int bf = rs / 220;
    const int f = bf % 24;
    const int b = bf / 24;
    const int rt = (b * 220 + p) * 24 + f;
    const float4* s = (const float4*)(src + (size_t)rt * 1024);
    float4* d = (float4*)(dst + (size_t)rs * 1024);
    d[threadIdx.x] = s[threadIdx.x];
}

// ---------------------------------------------------------------------------
// Orchestration (graph-capturable: kernel launches only)
// ---------------------------------------------------------------------------
extern "C" void kernel_launch(void* const* d_in, const int* in_sizes, int n_in,
                              void* d_out, int out_size)
{
    (void)in_sizes; (void)n_in; (void)out_size;
    const float* x       = (const float*)d_in[0];
    const float* w_sqkv  = (const float*)d_in[1];
    const float* w_sproj = (const float*)d_in[2];
    const float* b_sproj = (const float*)d_in[3];
    const float* w_tqkv  = (const float*)d_in[4];
    const float* w_tproj = (const float*)d_in[5];
    const float* b_tproj = (const float*)d_in[6];
    const float* sqg     = (const float*)d_in[7];
    const float* skg     = (const float*)d_in[8];
    const float* tqg     = (const float*)d_in[9];
    const float* tkg     = (const float*)d_in[10];
    float* out = (float*)d_out;

    float *bufA = nullptr, *bufB = nullptr, *bufC = nullptr;
    cudaGetSymbolAddress((void**)&bufA, g_bufA);
    cudaGetSymbolAddress((void**)&bufB, g_bufB);
    cudaGetSymbolAddress((void**)&bufC, g_bufC);

    const int M = 21120;
    const size_t smemS = (size_t)(2 * 220 * 65 + 8 * 220 + 512) * sizeof(float); // ~120.6 KB
    const size_t smemT = (size_t)(2 * 24 * 65 + 8 * 24 + 512) * sizeof(float);
    cudaFuncSetAttribute((const void*)attn_kernel,
                         cudaFuncAttributeMaxDynamicSharedMemorySize, (int)smemS);

    dim3 blk(256);

    // ---- spatial block (spatial row layout == input layout) ----
    sgemm_nt<<<dim3(24, M / 128), blk>>>(x, w_sqkv, bufA, nullptr, 3072);
    norm_rope<<<M * 4, blk>>>(bufA, sqg, skg, 220);
    attn_kernel<<<dim3(16, 96), blk, smemS>>>(bufA, bufB, 220);
    sgemm_nt<<<dim3(8, M / 128), blk>>>(bufB, w_sproj, bufC, b_sproj, 1024);

    // ---- spatial -> temporal layout ----
    s2t_kernel<<<M, blk>>>(bufC, bufB);

    // ---- temporal block ----
    sgemm_nt<<<dim3(24, M / 128), blk>>>(bufB, w_tqkv, bufA, nullptr, 3072);
    norm_rope<<<M * 4, blk>>>(bufA, tqg, tkg, 24);
    attn_kernel<<<dim3(16, 880), blk, smemT>>>(bufA, bufB, 24);
    sgemm_nt<<<dim3(8, M / 128), blk>>>(bufB, w_tproj, bufC, b_tproj, 1024);

    // ---- temporal -> output (spatial) layout ----
    t2s_kernel<<<M, blk>>>(bufC, out);
}

// round 8
// speedup vs baseline: 3.3419x; 2.0830x over previous
#include <cuda_runtime.h>
#include <cuda_fp16.h>
#include <cstdint>

// ---------------------------------------------------------------------------
// Problem constants:  x (4,5280,1024) fp32.  M = 21120 rows, K = 1024.
// Spatial attn: 96 seqs x 220.  Temporal: 880 seqs x 24.
// GEMMs via mma.sync.m16n8k16 fp16 (base-target PTX -> Blackwell HMMA).
// ---------------------------------------------------------------------------
#define MROWS 21120

// Scratch (static __device__ arrays — no allocation allowed)
__device__ __align__(1024) float          g_bufA[64880640ull];  // 21120*3072 qkv (fp32)
__device__ __align__(1024) float          g_bufC[21626880ull];  // 21120*1024 (fp32)
__device__ __align__(1024) unsigned short g_halfX[21626880ull]; // x in fp16
__device__ __align__(1024) unsigned short g_halfB[21626880ull]; // GEMM A operand (fp16)
__device__ __align__(1024) unsigned short g_halfW[8388608ull];  // weights in fp16

// ---------------------------------------------------------------------------
// PTX helpers (ALL base-target: cp.async sm_80, ldmatrix sm_75, mma sm_80)
// ---------------------------------------------------------------------------
__device__ __forceinline__ uint32_t su32(const void* p) {
    return (uint32_t)__cvta_generic_to_shared(p);
}
__device__ __forceinline__ void cp_async16(uint32_t s, const void* g) {
    asm volatile("cp.async.cg.shared.global [%0], [%1], 16;" :: "r"(s), "l"(g));
}
__device__ __forceinline__ void ldsm4(uint32_t* r, uint32_t a) {
    asm volatile("ldmatrix.sync.aligned.m8n8.x4.shared.b16 {%0,%1,%2,%3}, [%4];"
                 : "=r"(r[0]), "=r"(r[1]), "=r"(r[2]), "=r"(r[3]) : "r"(a));
}
__device__ __forceinline__ void mma16816(float* c, const uint32_t* a,
                                         uint32_t b0, uint32_t b1) {
    asm volatile(
        "mma.sync.aligned.m16n8k16.row.col.f32.f16.f16.f32 "
        "{%0,%1,%2,%3}, {%4,%5,%6,%7}, {%8,%9}, {%0,%1,%2,%3};"
        : "+f"(c[0]), "+f"(c[1]), "+f"(c[2]), "+f"(c[3])
        : "r"(a[0]), "r"(a[1]), "r"(a[2]), "r"(a[3]), "r"(b0), "r"(b1));
}

// ---------------------------------------------------------------------------
// HGEMM:  C[M,N] = A[M,1024] * W[N,1024]^T (+bias), fp16 in / fp32 out.
// 128x128x32 tiles, 128 threads (4 warps, warp tile 64x64), 4-stage cp.async.
// smem rows padded to 40 halfs (80B): ldmatrix 8-row phases conflict-free.
// ---------------------------------------------------------------------------
#define STG_A     10240u          // 128 rows * 80 B
#define STG_BYTES 20480u          // A + B
#define GSMEM     81920u          // 4 stages

__global__ __launch_bounds__(128, 2)
void hgemm(const unsigned short* __restrict__ A, const unsigned short* __restrict__ W,
           float* __restrict__ C, const float* __restrict__ bias, int Ntot)
{
    extern __shared__ __align__(128) char smem[];
    const uint32_t sbase = su32(smem);
    const int tid  = threadIdx.x;
    const int lane = tid & 31;
    const int wid  = tid >> 5;
    const int m0 = blockIdx.y * 128;
    const int n0 = blockIdx.x * 128;
    const int wm = (wid >> 1) * 64;       // warp row offset
    const int wn = (wid & 1) * 64;        // warp col offset

    // stage loader: thread -> (row lr + 32i, 16B granule lg)
    const int lg = tid & 3;
    const int lr = tid >> 2;
    const unsigned short* gA = A + (size_t)(m0 + lr) * 1024 + lg * 8;
    const unsigned short* gB = W + (size_t)(n0 + lr) * 1024 + lg * 8;
    const uint32_t sOff = (uint32_t)(lr * 80 + lg * 16);

#define LOAD_STAGE(kt, slot)                                                  \
    {                                                                         \
        const uint32_t sa = sbase + (uint32_t)(slot) * STG_BYTES + sOff;      \
        const uint32_t sb = sa + STG_A;                                       \
        const size_t go = (size_t)(kt) * 32;                                  \
        _Pragma("unroll")                                                     \
        for (int i = 0; i < 4; i++) {                                         \
            cp_async16(sa + i * 2560u, gA + go + (size_t)(32 * i) * 1024);    \
            cp_async16(sb + i * 2560u, gB + go + (size_t)(32 * i) * 1024);    \
        }                                                                     \
        asm volatile("cp.async.commit_group;" ::: "memory");                  \
    }

    float c[4][8][4];
#pragma unroll
    for (int mt = 0; mt < 4; mt++)
#pragma unroll
        for (int nt = 0; nt < 8; nt++)
#pragma unroll
            for (int i = 0; i < 4; i++) c[mt][nt][i] = 0.f;

    LOAD_STAGE(0, 0);
    LOAD_STAGE(1, 1);
    LOAD_STAGE(2, 2);

    // precomputed fragment address components
    const uint32_t aRow = (uint32_t)(wm + (lane & 15));          // + mt*16
    const uint32_t aCol = (uint32_t)(((lane >> 4) & 1) * 16);    // + ks*32
    const uint32_t bRow = (uint32_t)(wn + ((lane >> 4) << 3) + (lane & 7)); // + np*16
    const uint32_t bCol = (uint32_t)(((lane >> 3) & 1) * 16);    // + ks*32

    for (int kt = 0; kt < 32; kt++) {
        asm volatile("cp.async.wait_group 2;" ::: "memory");
        __syncthreads();
        if (kt + 3 < 32) LOAD_STAGE(kt + 3, (kt + 3) & 3);

        const uint32_t stA = sbase + (uint32_t)(kt & 3) * STG_BYTES;
        const uint32_t stB = stA + STG_A;
#pragma unroll
        for (int ks = 0; ks < 2; ks++) {
            uint32_t a[4][4], b[4][4];
#pragma unroll
            for (int mt = 0; mt < 4; mt++)
                ldsm4(a[mt], stA + (aRow + mt * 16) * 80 + ks * 32 + aCol);
#pragma unroll
            for (int np = 0; np < 4; np++)
                ldsm4(b[np], stB + (bRow + np * 16) * 80 + ks * 32 + bCol);
#pragma unroll
            for (int mt = 0; mt < 4; mt++)
#pragma unroll
                for (int np = 0; np < 4; np++) {
                    mma16816(c[mt][2 * np],     a[mt], b[np][0], b[np][1]);
                    mma16816(c[mt][2 * np + 1], a[mt], b[np][2], b[np][3]);
                }
        }
    }

    // epilogue (+bias), fp32 float2 stores
    const int grp = lane >> 2;
    const int qd  = (lane & 3) * 2;
#pragma unroll
    for (int mt = 0; mt < 4; mt++) {
        const int r0 = m0 + wm + mt * 16 + grp;
#pragma unroll
        for (int nt = 0; nt < 8; nt++) {
            const int cn = n0 + wn + nt * 8 + qd;
            float bx = 0.f, by = 0.f;
            if (bias) { bx = bias[cn]; by = bias[cn + 1]; }
            *(float2*)(C + (size_t)r0 * Ntot + cn) =
                make_float2(c[mt][nt][0] + bx, c[mt][nt][1] + by);
            *(float2*)(C + (size_t)(r0 + 8) * Ntot + cn) =
                make_float2(c[mt][nt][2] + bx, c[mt][nt][3] + by);
        }
    }
#undef LOAD_STAGE
}

// ---------------------------------------------------------------------------
// fp32 -> fp16 conversion (RN)
// ---------------------------------------------------------------------------
__global__ void cvt_half(const float4* __restrict__ s, uint2* __restrict__ d, int n4)
{
    const int i = blockIdx.x * 256 + threadIdx.x;
    if (i < n4) {
        float4 v = s[i];
        union { __half2 h[2]; uint2 u; } p;
        p.h[0] = __floats2half2_rn(v.x, v.y);
        p.h[1] = __floats2half2_rn(v.z, v.w);
        d[i] = p.u;
    }
}

// ---------------------------------------------------------------------------
// Fused RMSNorm + RoPE, in place on q,k of qkv (M x 3072, fp32).
// ---------------------------------------------------------------------------
__global__ void norm_rope(float* __restrict__ qkv, const float* __restrict__ qg,
                          const float* __restrict__ kg, int seqlen)
{
    const int warp = (blockIdx.x << 3) + (threadIdx.x >> 5);
    const int lane = threadIdx.x & 31;
    const int row  = warp >> 5;
    const int rem  = warp & 31;
    const int comp = rem >> 4;
    const int head = rem & 15;

    float* p = qkv + (size_t)row * 3072 + comp * 1024 + head * 64 + 2 * lane;
    float2 v = *(float2*)p;
    float ss = v.x * v.x + v.y * v.y;
#pragma unroll
    for (int o = 16; o > 0; o >>= 1) ss += __shfl_xor_sync(0xffffffffu, ss, o);
    const float inv = rsqrtf(ss * (1.0f / 64.0f) + 1e-6f);

    const float* g = comp ? kg : qg;
    const float x0 = v.x * inv * g[2 * lane];
    const float x1 = v.y * inv * g[2 * lane + 1];

    const int pos = row % seqlen;
    const float theta = exp2f((float)lane * (-13.287712379549449f / 32.0f));
    float s, c;
    sincosf((float)pos * theta, &s, &c);
    *(float2*)p = make_float2(x0 * c - x1 * s, x1 * c + x0 * s);
}

// ---------------------------------------------------------------------------
// Attention (fp32 math, fp16 output feeding the proj GEMM).
// ---------------------------------------------------------------------------
__global__ void attn_kernel(const float* __restrict__ qkv,
                            unsigned short* __restrict__ out, int S)
{
    extern __shared__ float sm[];
    const int h = blockIdx.x;
    const int n = blockIdx.y;
    const int tid = threadIdx.x;
    const int w = tid >> 5;
    const int lane = tid & 31;

    float* sK = sm;
    float* sV = sK + S * 65;
    float* sP = sV + S * 65;
    float* sQ = sP + 8 * S;

    const float* base = qkv + (size_t)n * S * 3072 + h * 64;
    for (int idx = tid; idx < S * 64; idx += 256) {
        const int s = idx >> 6, d = idx & 63;
        sK[s * 65 + d] = base[(size_t)s * 3072 + 1024 + d];
        sV[s * 65 + d] = base[(size_t)s * 3072 + 2048 + d];
    }
    __syncthreads();

    for (int r = w; r < S; r += 8) {
        {
            float2 q2 = *(const float2*)(base + (size_t)r * 3072 + 2 * lane);
            sQ[w * 64 + 2 * lane]     = q2.x;
            sQ[w * 64 + 2 * lane + 1] = q2.y;
        }
        __syncwarp();

        float sc[7];
        float mx = -1e30f;
        int cnt = 0;
        for (int s = lane; s < S; s += 32) {
            float dot = 0.f;
            const float* kr = sK + s * 65;
            const float* qr = sQ + w * 64;
#pragma unroll
            for (int d = 0; d < 64; d++) dot = fmaf(qr[d], kr[d], dot);
            dot *= 0.125f;
            sc[cnt++] = dot;
            mx = fmaxf(mx, dot);
        }
#pragma unroll
        for (int o = 16; o > 0; o >>= 1) mx = fmaxf(mx, __shfl_xor_sync(0xffffffffu, mx, o));
        float sum = 0.f;
#pragma unroll
        for (int i = 0; i < 7; i++)
            if (i < cnt) { sc[i] = __expf(sc[i] - mx); sum += sc[i]; }
#pragma unroll
        for (int o = 16; o > 0; o >>= 1) sum += __shfl_xor_sync(0xffffffffu, sum, o);
        const float isum = 1.0f / sum;
        {
            int i = 0;
            for (int s = lane; s < S; s += 32) sP[w * S + s] = sc[i++] * isum;
        }
        __syncwarp();

        float a0 = 0.f, a1 = 0.f;
        const float* pw = sP + w * S;
        for (int s = 0; s < S; s++) {
            const float pp = pw[s];
            a0 = fmaf(pp, sV[s * 65 + lane], a0);
            a1 = fmaf(pp, sV[s * 65 + lane + 32], a1);
        }
        __half* op = (__half*)(out + ((size_t)n * S + r) * 1024 + h * 64);
        op[lane]      = __float2half_rn(a0);
        op[lane + 32] = __float2half_rn(a1);
        __syncwarp();
    }
}

// ---------------------------------------------------------------------------
// Row permutes.  s2t: fp32 -> fp16 (feeds temporal QKV GEMM).  t2s: exact fp32.
// ---------------------------------------------------------------------------
__global__ void s2t_kernel(const float* __restrict__ src, uint2* __restrict__ dst)
{
    const int rt = blockIdx.x;
    const int f = rt % 24;
    const int bp = rt / 24;
    const int p = bp % 220;
    const int b = bp / 220;
    const int rs = (b * 24 + f) * 220 + p;
    float4 v = ((const float4*)(src + (size_t)rs * 1024))[threadIdx.x];
    union { __half2 h[2]; uint2 u; } pk;
    pk.h[0] = __floats2half2_rn(v.x, v.y);
    pk.h[1] = __floats2half2_rn(v.z, v.w);
    dst[(size_t)rt * 256 + threadIdx.x] = pk.u;
}
__global__ void t2s_kernel(const float* __restrict__ src, float* __restrict__ dst)
{
    const int rs = blockIdx.x;
    const int p = rs % 220;
    const int bf = rs / 220;
    const int f = bf % 24;
    const int b = bf / 24;
    const int rt = (b * 220 + p) * 24 + f;
    ((float4*)(dst + (size_t)rs * 1024))[threadIdx.x] =
        ((const float4*)(src + (size_t)rt * 1024))[threadIdx.x];
}

// ---------------------------------------------------------------------------
// Orchestration (graph-capturable: kernel launches only)
// ---------------------------------------------------------------------------
extern "C" void kernel_launch(void* const* d_in, const int* in_sizes, int n_in,
                              void* d_out, int out_size)
{
    (void)in_sizes; (void)n_in; (void)out_size;
    const float* x       = (const float*)d_in[0];
    const float* w_sqkv  = (const float*)d_in[1];
    const float* w_sproj = (const float*)d_in[2];
    const float* b_sproj = (const float*)d_in[3];
    const float* w_tqkv  = (const float*)d_in[4];
    const float* w_tproj = (const float*)d_in[5];
    const float* b_tproj = (const float*)d_in[6];
    const float* sqg     = (const float*)d_in[7];
    const float* skg     = (const float*)d_in[8];
    const float* tqg     = (const float*)d_in[9];
    const float* tkg     = (const float*)d_in[10];
    float* out = (float*)d_out;

    float *bufA, *bufC;
    unsigned short *hX, *hB, *hW;
    cudaGetSymbolAddress((void**)&bufA, g_bufA);
    cudaGetSymbolAddress((void**)&bufC, g_bufC);
    cudaGetSymbolAddress((void**)&hX, g_halfX);
    cudaGetSymbolAddress((void**)&hB, g_halfB);
    cudaGetSymbolAddress((void**)&hW, g_halfW);

    unsigned short* wQS = hW;                 // 3072x1024
    unsigned short* wPS = hW + 3145728;       // 1024x1024
    unsigned short* wQT = hW + 4194304;       // 3072x1024
    unsigned short* wPT = hW + 7340032;       // 1024x1024

    const size_t smemS = (size_t)(2 * 220 * 65 + 8 * 220 + 512) * sizeof(float);
    const size_t smemT = (size_t)(2 * 24 * 65 + 8 * 24 + 512) * sizeof(float);
    cudaFuncSetAttribute((const void*)attn_kernel,
                         cudaFuncAttributeMaxDynamicSharedMemorySize, (int)smemS);
    cudaFuncSetAttribute((const void*)hgemm,
                         cudaFuncAttributeMaxDynamicSharedMemorySize, (int)GSMEM);

    dim3 blk(256);
    const int M = MROWS;

    // ---- fp16 operand preparation ----
    cvt_half<<<21120, blk>>>((const float4*)x,       (uint2*)hX,  5406720);
    cvt_half<<<3072,  blk>>>((const float4*)w_sqkv,  (uint2*)wQS, 786432);
    cvt_half<<<1024,  blk>>>((const float4*)w_sproj, (uint2*)wPS, 262144);
    cvt_half<<<3072,  blk>>>((const float4*)w_tqkv,  (uint2*)wQT, 786432);
    cvt_half<<<1024,  blk>>>((const float4*)w_tproj, (uint2*)wPT, 262144);

    // ---- spatial block ----
    hgemm<<<dim3(24, M / 128), 128, GSMEM>>>(hX, wQS, bufA, nullptr, 3072);
    norm_rope<<<M * 4, blk>>>(bufA, sqg, skg, 220);
    attn_kernel<<<dim3(16, 96), blk, smemS>>>(bufA, hB, 220);
    hgemm<<<dim3(8, M / 128), 128, GSMEM>>>(hB, wPS, bufC, b_sproj, 1024);

    // ---- spatial -> temporal layout (fp16 for next GEMM) ----
    s2t_kernel<<<M, blk>>>(bufC, (uint2*)hB);

    // ---- temporal block ----
    hgemm<<<dim3(24, M / 128), 128, GSMEM>>>(hB, wQT, bufA, nullptr, 3072);
    norm_rope<<<M * 4, blk>>>(bufA, tqg, tkg, 24);
    attn_kernel<<<dim3(16, 880), blk, smemT>>>(bufA, hB, 24);
    hgemm<<<dim3(8, M / 128), 128, GSMEM>>>(hB, wPT, bufC, b_tproj, 1024);

    // ---- temporal -> output layout (exact fp32) ----
    t2s_kernel<<<M, blk>>>(bufC, out);
}

// round 9
// speedup vs baseline: 5.6794x; 1.6994x over previous
#include <cuda_runtime.h>
#include <cuda_fp16.h>
#include <cstdint>

// ---------------------------------------------------------------------------
// Problem constants:  x (4,5280,1024) fp32.  M = 21120 rows, K = 1024.
// Spatial attn: 96 seqs x 220.  Temporal: 880 seqs x 24.
// GEMMs via mma.sync.m16n8k16 fp16.  RMSNorm+RoPE fused into QKV epilogue;
// s2t / t2s row permutes fused into the projection epilogues.
// ---------------------------------------------------------------------------
#define MROWS 21120

// Scratch (static __device__ arrays — no allocation allowed)
__device__ __align__(1024) float          g_bufA[64880640ull];  // qkv fp32
__device__ __align__(1024) float2         g_rope[7040];         // 220 x 32 (cos,sin)
__device__ __align__(1024) unsigned short g_halfX[21626880ull]; // x fp16 / temporal in
__device__ __align__(1024) unsigned short g_halfB[21626880ull]; // attn out fp16
__device__ __align__(1024) unsigned short g_halfW[8388608ull];  // weights fp16

// ---------------------------------------------------------------------------
// PTX helpers (base-target: cp.async sm_80, ldmatrix sm_75, mma sm_80)
// ---------------------------------------------------------------------------
__device__ __forceinline__ uint32_t su32(const void* p) {
    return (uint32_t)__cvta_generic_to_shared(p);
}
__device__ __forceinline__ void cp_async16(uint32_t s, const void* g) {
    asm volatile("cp.async.cg.shared.global [%0], [%1], 16;" :: "r"(s), "l"(g));
}
__device__ __forceinline__ void ldsm4(uint32_t* r, uint32_t a) {
    asm volatile("ldmatrix.sync.aligned.m8n8.x4.shared.b16 {%0,%1,%2,%3}, [%4];"
                 : "=r"(r[0]), "=r"(r[1]), "=r"(r[2]), "=r"(r[3]) : "r"(a));
}
__device__ __forceinline__ void mma16816(float* c, const uint32_t* a,
                                         uint32_t b0, uint32_t b1) {
    asm volatile(
        "mma.sync.aligned.m16n8k16.row.col.f32.f16.f16.f32 "
        "{%0,%1,%2,%3}, {%4,%5,%6,%7}, {%8,%9}, {%0,%1,%2,%3};"
        : "+f"(c[0]), "+f"(c[1]), "+f"(c[2]), "+f"(c[3])
        : "r"(a[0]), "r"(a[1]), "r"(a[2]), "r"(a[3]), "r"(b0), "r"(b1));
}

// ---------------------------------------------------------------------------
// HGEMM:  C[M,N] = A[M,1024] * W[N,1024]^T, fp16 in / fp32 accum.
// 128x128x32 tiles, 128 threads (4 warps, warp tile 64x64), 4-stage cp.async.
// MODE 1: QKV — fused RMSNorm (per-head) + RoPE on q,k; fp32 out, no bias.
// MODE 2: proj — +bias, fp16 out at s2t-permuted rows.
// MODE 3: proj — +bias, fp32 out at t2s-permuted rows.
// ---------------------------------------------------------------------------
#define STG_A     10240u          // 128 rows * 80 B
#define STG_BYTES 20480u          // A + B
#define GSMEM     81920u          // 4 stages

template<int MODE>
__global__ __launch_bounds__(128, 2)
void hgemm(const unsigned short* __restrict__ A, const unsigned short* __restrict__ W,
           void* __restrict__ Cout, const float* __restrict__ bias, int Ntot,
           const float* __restrict__ qg, const float* __restrict__ kg,
           int seqlen, const float2* __restrict__ rope)
{
    extern __shared__ __align__(128) char smem[];
    const uint32_t sbase = su32(smem);
    const int tid  = threadIdx.x;
    const int lane = tid & 31;
    const int wid  = tid >> 5;
    const int m0 = blockIdx.y * 128;
    const int n0 = blockIdx.x * 128;
    const int wm = (wid >> 1) * 64;
    const int wn = (wid & 1) * 64;

    const int lg = tid & 3;
    const int lr = tid >> 2;
    const unsigned short* gA = A + (size_t)(m0 + lr) * 1024 + lg * 8;
    const unsigned short* gB = W + (size_t)(n0 + lr) * 1024 + lg * 8;
    const uint32_t sOff = (uint32_t)(lr * 80 + lg * 16);

#define LOAD_STAGE(kt, slot)                                                  \
    {                                                                         \
        const uint32_t sa = sbase + (uint32_t)(slot) * STG_BYTES + sOff;      \
        const uint32_t sb = sa + STG_A;                                       \
        const size_t go = (size_t)(kt) * 32;                                  \
        _Pragma("unroll")                                                     \
        for (int i = 0; i < 4; i++) {                                         \
            cp_async16(sa + i * 2560u, gA + go + (size_t)(32 * i) * 1024);    \
            cp_async16(sb + i * 2560u, gB + go + (size_t)(32 * i) * 1024);    \
        }                                                                     \
        asm volatile("cp.async.commit_group;" ::: "memory");                  \
    }

    float c[4][8][4];
#pragma unroll
    for (int mt = 0; mt < 4; mt++)
#pragma unroll
        for (int nt = 0; nt < 8; nt++)
#pragma unroll
            for (int i = 0; i < 4; i++) c[mt][nt][i] = 0.f;

    LOAD_STAGE(0, 0);
    LOAD_STAGE(1, 1);
    LOAD_STAGE(2, 2);

    const uint32_t aRow = (uint32_t)(wm + (lane & 15));
    const uint32_t aCol = (uint32_t)(((lane >> 4) & 1) * 16);
    const uint32_t bRow = (uint32_t)(wn + ((lane >> 4) << 3) + (lane & 7));
    const uint32_t bCol = (uint32_t)(((lane >> 3) & 1) * 16);

    for (int kt = 0; kt < 32; kt++) {
        asm volatile("cp.async.wait_group 2;" ::: "memory");
        __syncthreads();
        if (kt + 3 < 32) LOAD_STAGE(kt + 3, (kt + 3) & 3);

        const uint32_t stA = sbase + (uint32_t)(kt & 3) * STG_BYTES;
        const uint32_t stB = stA + STG_A;
#pragma unroll
        for (int ks = 0; ks < 2; ks++) {
            uint32_t a[4][4], b[4][4];
#pragma unroll
            for (int mt = 0; mt < 4; mt++)
                ldsm4(a[mt], stA + (aRow + mt * 16) * 80 + ks * 32 + aCol);
#pragma unroll
            for (int np = 0; np < 4; np++)
                ldsm4(b[np], stB + (bRow + np * 16) * 80 + ks * 32 + bCol);
#pragma unroll
            for (int mt = 0; mt < 4; mt++)
#pragma unroll
                for (int np = 0; np < 4; np++) {
                    mma16816(c[mt][2 * np],     a[mt], b[np][0], b[np][1]);
                    mma16816(c[mt][2 * np + 1], a[mt], b[np][2], b[np][3]);
                }
        }
    }
#undef LOAD_STAGE

    const int grp = lane >> 2;
    const int qd  = (lane & 3) * 2;

    if (MODE == 1) {
        // ---- QKV epilogue: fused RMSNorm + RoPE on q,k; plain store for v ----
        float* C = (float*)Cout;
        const int comp = n0 >> 10;             // 0=q 1=k 2=v
        if (comp == 2) {
#pragma unroll
            for (int mt = 0; mt < 4; mt++) {
                const int r0 = m0 + wm + mt * 16 + grp;
#pragma unroll
                for (int nt = 0; nt < 8; nt++) {
                    const int cn = n0 + wn + nt * 8 + qd;
                    *(float2*)(C + (size_t)r0 * Ntot + cn) =
                        make_float2(c[mt][nt][0], c[mt][nt][1]);
                    *(float2*)(C + (size_t)(r0 + 8) * Ntot + cn) =
                        make_float2(c[mt][nt][2], c[mt][nt][3]);
                }
            }
        } else {
            const float* g = comp ? kg : qg;
            float2 gv[8];
#pragma unroll
            for (int nt = 0; nt < 8; nt++)
                gv[nt] = *(const float2*)(g + nt * 8 + qd);
#pragma unroll
            for (int mt = 0; mt < 4; mt++) {
                const int r0 = m0 + wm + mt * 16 + grp;
                float ss0 = 0.f, ss1 = 0.f;
#pragma unroll
                for (int nt = 0; nt < 8; nt++) {
                    ss0 = fmaf(c[mt][nt][0], c[mt][nt][0], ss0);
                    ss0 = fmaf(c[mt][nt][1], c[mt][nt][1], ss0);
                    ss1 = fmaf(c[mt][nt][2], c[mt][nt][2], ss1);
                    ss1 = fmaf(c[mt][nt][3], c[mt][nt][3], ss1);
                }
                ss0 += __shfl_xor_sync(0xffffffffu, ss0, 1);
                ss0 += __shfl_xor_sync(0xffffffffu, ss0, 2);
                ss1 += __shfl_xor_sync(0xffffffffu, ss1, 1);
                ss1 += __shfl_xor_sync(0xffffffffu, ss1, 2);
                const float inv0 = rsqrtf(ss0 * (1.0f / 64.0f) + 1e-6f);
                const float inv1 = rsqrtf(ss1 * (1.0f / 64.0f) + 1e-6f);
                const float2* rp0 = rope + (r0 % seqlen) * 32 + (lane & 3);
                const float2* rp1 = rope + ((r0 + 8) % seqlen) * 32 + (lane & 3);
#pragma unroll
                for (int nt = 0; nt < 8; nt++) {
                    const float2 cs0 = rp0[nt * 4];
                    const float2 cs1 = rp1[nt * 4];
                    const float v0 = c[mt][nt][0] * inv0 * gv[nt].x;
                    const float v1 = c[mt][nt][1] * inv0 * gv[nt].y;
                    const float w0 = c[mt][nt][2] * inv1 * gv[nt].x;
                    const float w1 = c[mt][nt][3] * inv1 * gv[nt].y;
                    const int cn = n0 + wn + nt * 8 + qd;
                    *(float2*)(C + (size_t)r0 * Ntot + cn) =
                        make_float2(v0 * cs0.x - v1 * cs0.y, v1 * cs0.x + v0 * cs0.y);
                    *(float2*)(C + (size_t)(r0 + 8) * Ntot + cn) =
                        make_float2(w0 * cs1.x - w1 * cs1.y, w1 * cs1.x + w0 * cs1.y);
                }
            }
        }
    } else if (MODE == 2) {
        // ---- proj epilogue: +bias, fp16 out at s2t-permuted rows ----
        __half2* C = (__half2*)Cout;           // row stride 512 half2
#pragma unroll
        for (int mt = 0; mt < 4; mt++) {
            const int r0 = m0 + wm + mt * 16 + grp;
#pragma unroll
            for (int hf = 0; hf < 2; hf++) {
                const int r = r0 + 8 * hf;
                const int b = r / 5280;
                const int f = (r % 5280) / 220;
                const int p = r % 220;
                const int rt = (b * 220 + p) * 24 + f;
#pragma unroll
                for (int nt = 0; nt < 8; nt++) {
                    const int cn = n0 + wn + nt * 8 + qd;
                    const float x0 = c[mt][nt][2 * hf]     + bias[cn];
                    const float x1 = c[mt][nt][2 * hf + 1] + bias[cn + 1];
                    C[(size_t)rt * 512 + cn / 2] = __floats2half2_rn(x0, x1);
                }
            }
        }
    } else {
        // ---- proj epilogue: +bias, fp32 out at t2s-permuted rows ----
        float* C = (float*)Cout;
#pragma unroll
        for (int mt = 0; mt < 4; mt++) {
            const int r0 = m0 + wm + mt * 16 + grp;
#pragma unroll
            for (int hf = 0; hf < 2; hf++) {
                const int r = r0 + 8 * hf;
                const int f = r % 24;
                const int p = (r % 5280) / 24;
                const int b = r / 5280;
                const int rs = (b * 24 + f) * 220 + p;
#pragma unroll
                for (int nt = 0; nt < 8; nt++) {
                    const int cn = n0 + wn + nt * 8 + qd;
                    *(float2*)(C + (size_t)rs * Ntot + cn) =
                        make_float2(c[mt][nt][2 * hf]     + bias[cn],
                                    c[mt][nt][2 * hf + 1] + bias[cn + 1]);
                }
            }
        }
    }
}

// ---------------------------------------------------------------------------
// RoPE cos/sin table init: 220 positions x 32 dim-pairs.
// ---------------------------------------------------------------------------
__global__ void init_rope(float2* t)
{
    const int pos = blockIdx.x;
    const int j = threadIdx.x;
    const float theta = exp2f((float)j * (-13.287712379549449f / 32.0f));
    float s, c;
    sincosf((float)pos * theta, &s, &c);
    t[pos * 32 + j] = make_float2(c, s);
}

// ---------------------------------------------------------------------------
// fp32 -> fp16 conversion (RN)
// ---------------------------------------------------------------------------
__global__ void cvt_half(const float4* __restrict__ s, uint2* __restrict__ d, int n4)
{
    const int i = blockIdx.x * 256 + threadIdx.x;
    if (i < n4) {
        float4 v = s[i];
        union { __half2 h[2]; uint2 u; } p;
        p.h[0] = __floats2half2_rn(v.x, v.y);
        p.h[1] = __floats2half2_rn(v.z, v.w);
        d[i] = p.u;
    }
}

// ---------------------------------------------------------------------------
// Attention: one CTA per (head, seq).  K,V staged as fp16 in smem (stride 66
// halfs -> conflict-free), fp32 math.  4-accumulator dot, x4-unrolled PV.
// smem spatial ~66KB -> 3 CTAs/SM.  Output fp16 (feeds proj GEMM).
// ---------------------------------------------------------------------------
__global__ void attn_kernel(const float* __restrict__ qkv,
                            unsigned short* __restrict__ out, int S)
{
    extern __shared__ __align__(16) char smraw[];
    const int h = blockIdx.x;
    const int n = blockIdx.y;
    const int tid = threadIdx.x;
    const int w = tid >> 5;
    const int lane = tid & 31;

    float*  sP = (float*)smraw;            // 8 * S
    float*  sQ = sP + 8 * S;               // 8 * 64
    __half* sK = (__half*)(sQ + 512);      // S * 66
    __half* sV = sK + S * 66;              // S * 66

    const float* base = qkv + (size_t)n * S * 3072 + h * 64;
    for (int idx = tid; idx < S * 64; idx += 256) {
        const int s = idx >> 6, d = idx & 63;
        sK[s * 66 + d] = __float2half_rn(base[(size_t)s * 3072 + 1024 + d]);
        sV[s * 66 + d] = __float2half_rn(base[(size_t)s * 3072 + 2048 + d]);
    }
    __syncthreads();

    for (int r = w; r < S; r += 8) {
        {
            float2 q2 = *(const float2*)(base + (size_t)r * 3072 + 2 * lane);
            sQ[w * 64 + 2 * lane]     = q2.x;
            sQ[w * 64 + 2 * lane + 1] = q2.y;
        }
        __syncwarp();
        const float* qr = sQ + w * 64;

        float sc[7];
        float mx = -1e30f;
        int cnt = 0;
        for (int s = lane; s < S; s += 32) {
            const uint32_t* kr = (const uint32_t*)(sK + s * 66);
            float d0 = 0.f, d1 = 0.f, d2 = 0.f, d3 = 0.f;
#pragma unroll
            for (int t = 0; t < 16; t++) {
                const float4 q4 = *(const float4*)(qr + 4 * t);
                const uint32_t ka = kr[2 * t];
                const uint32_t kb = kr[2 * t + 1];
                const float2 k0 = __half22float2(*(const __half2*)&ka);
                const float2 k1 = __half22float2(*(const __half2*)&kb);
                d0 = fmaf(q4.x, k0.x, d0);
                d1 = fmaf(q4.y, k0.y, d1);
                d2 = fmaf(q4.z, k1.x, d2);
                d3 = fmaf(q4.w, k1.y, d3);
            }
            const float dot = ((d0 + d1) + (d2 + d3)) * 0.125f;
            sc[cnt++] = dot;
            mx = fmaxf(mx, dot);
        }
#pragma unroll
        for (int o = 16; o > 0; o >>= 1) mx = fmaxf(mx, __shfl_xor_sync(0xffffffffu, mx, o));
        float sum = 0.f;
#pragma unroll
        for (int i = 0; i < 7; i++)
            if (i < cnt) { sc[i] = __expf(sc[i] - mx); sum += sc[i]; }
#pragma unroll
        for (int o = 16; o > 0; o >>= 1) sum += __shfl_xor_sync(0xffffffffu, sum, o);
        const float isum = 1.0f / sum;
        {
            int i = 0;
            for (int s = lane; s < S; s += 32) sP[w * S + s] = sc[i++] * isum;
        }
        __syncwarp();

        float a0 = 0.f, a1 = 0.f, a2 = 0.f, a3 = 0.f;
        float b0 = 0.f, b1 = 0.f, b2 = 0.f, b3 = 0.f;
        const float* pw = sP + w * S;
        const __half* v0p = sV + lane;
        const __half* v1p = sV + lane + 32;
        for (int s = 0; s < S; s += 4) {
            const float p0 = pw[s],     p1 = pw[s + 1];
            const float p2 = pw[s + 2], p3 = pw[s + 3];
            a0 = fmaf(p0, __half2float(v0p[(s)     * 66]), a0);
            b0 = fmaf(p0, __half2float(v1p[(s)     * 66]), b0);
            a1 = fmaf(p1, __half2float(v0p[(s + 1) * 66]), a1);
            b1 = fmaf(p1, __half2float(v1p[(s + 1) * 66]), b1);
            a2 = fmaf(p2, __half2float(v0p[(s + 2) * 66]), a2);
            b2 = fmaf(p2, __half2float(v1p[(s + 2) * 66]), b2);
            a3 = fmaf(p3, __half2float(v0p[(s + 3) * 66]), a3);
            b3 = fmaf(p3, __half2float(v1p[(s + 3) * 66]), b3);
        }
        __half* op = (__half*)(out + ((size_t)n * S + r) * 1024 + h * 64);
        op[lane]      = __float2half_rn((a0 + a1) + (a2 + a3));
        op[lane + 32] = __float2half_rn((b0 + b1) + (b2 + b3));
        __syncwarp();
    }
}

// ---------------------------------------------------------------------------
// Orchestration (graph-capturable: kernel launches only)
// ---------------------------------------------------------------------------
extern "C" void kernel_launch(void* const* d_in, const int* in_sizes, int n_in,
                              void* d_out, int out_size)
{
    (void)in_sizes; (void)n_in; (void)out_size;
    const float* x       = (const float*)d_in[0];
    const float* w_sqkv  = (const float*)d_in[1];
    const float* w_sproj = (const float*)d_in[2];
    const float* b_sproj = (const float*)d_in[3];
    const float* w_tqkv  = (const float*)d_in[4];
    const float* w_tproj = (const float*)d_in[5];
    const float* b_tproj = (const float*)d_in[6];
    const float* sqg     = (const float*)d_in[7];
    const float* skg     = (const float*)d_in[8];
    const float* tqg     = (const float*)d_in[9];
    const float* tkg     = (const float*)d_in[10];
    float* out = (float*)d_out;

    float* bufA;
    float2* rope;
    unsigned short *hX, *hB, *hW;
    cudaGetSymbolAddress((void**)&bufA, g_bufA);
    cudaGetSymbolAddress((void**)&rope, g_rope);
    cudaGetSymbolAddress((void**)&hX, g_halfX);
    cudaGetSymbolAddress((void**)&hB, g_halfB);
    cudaGetSymbolAddress((void**)&hW, g_halfW);

    unsigned short* wQS = hW;                 // 3072x1024
    unsigned short* wPS = hW + 3145728;       // 1024x1024
    unsigned short* wQT = hW + 4194304;       // 3072x1024
    unsigned short* wPT = hW + 7340032;       // 1024x1024

    const size_t smemS = (size_t)(8 * 220 * 4 + 2048 + 2 * 220 * 66 * 2 + 64);
    const size_t smemT = (size_t)(8 * 24 * 4 + 2048 + 2 * 24 * 66 * 2 + 64);
    cudaFuncSetAttribute((const void*)attn_kernel,
                         cudaFuncAttributeMaxDynamicSharedMemorySize, (int)smemS);
    cudaFuncSetAttribute((const void*)hgemm<1>,
                         cudaFuncAttributeMaxDynamicSharedMemorySize, (int)GSMEM);
    cudaFuncSetAttribute((const void*)hgemm<2>,
                         cudaFuncAttributeMaxDynamicSharedMemorySize, (int)GSMEM);
    cudaFuncSetAttribute((const void*)hgemm<3>,
                         cudaFuncAttributeMaxDynamicSharedMemorySize, (int)GSMEM);

    dim3 blk(256);
    const int M = MROWS;

    // ---- operand preparation ----
    init_rope<<<220, 32>>>(rope);
    cvt_half<<<21120, blk>>>((const float4*)x,       (uint2*)hX,  5406720);
    cvt_half<<<3072,  blk>>>((const float4*)w_sqkv,  (uint2*)wQS, 786432);
    cvt_half<<<1024,  blk>>>((const float4*)w_sproj, (uint2*)wPS, 262144);
    cvt_half<<<3072,  blk>>>((const float4*)w_tqkv,  (uint2*)wQT, 786432);
    cvt_half<<<1024,  blk>>>((const float4*)w_tproj, (uint2*)wPT, 262144);

    // ---- spatial block ----
    hgemm<1><<<dim3(24, M / 128), 128, GSMEM>>>(hX, wQS, bufA, nullptr, 3072,
                                                sqg, skg, 220, rope);
    attn_kernel<<<dim3(16, 96), blk, smemS>>>(bufA, hB, 220);
    // proj + s2t permute + fp16 (output becomes temporal-layout GEMM input in hX)
    hgemm<2><<<dim3(8, M / 128), 128, GSMEM>>>(hB, wPS, hX, b_sproj, 1024,
                                               nullptr, nullptr, 0, nullptr);

    // ---- temporal block ----
    hgemm<1><<<dim3(24, M / 128), 128, GSMEM>>>(hX, wQT, bufA, nullptr, 3072,
                                                tqg, tkg, 24, rope);
    attn_kernel<<<dim3(16, 880), blk, smemT>>>(bufA, hB, 24);
    // proj + t2s permute, fp32 straight to d_out
    hgemm<3><<<dim3(8, M / 128), 128, GSMEM>>>(hB, wPT, out, b_tproj, 1024,
                                               nullptr, nullptr, 0, nullptr);
}